// round 1
// baseline (speedup 1.0000x reference)
#include <cuda_runtime.h>
#include <math.h>

#define DM   256
#define NH   8
#define DK   32
#define DFF  1024
#define NLAY 6
#define BB   8
#define LL   1024
#define TT   (BB * LL)     /* 8192 tokens */
#define TOPK 256
#define EPSF 1e-5f

/* ------------------------------------------------------------------ */
/* scratch (static device globals: no runtime allocation)             */
/* ------------------------------------------------------------------ */
__device__ float g_H[TT * DM];
__device__ float g_S[TT * DM];
__device__ float g_QKV[TT * 3 * DM];
__device__ float g_O[TT * DM];
__device__ float g_P[TT * DM];
__device__ float g_F[TT * DFF];
__device__ float g_VOL[BB * DFF];

/* ------------------------------------------------------------------ */
/* embed: h = x @ in_w + in_b + PE                                     */
/* ------------------------------------------------------------------ */
__global__ void embed_kernel(const float* __restrict__ x,
                             const float* __restrict__ in_w,
                             const float* __restrict__ in_b) {
    int t = blockIdx.x;
    int d = threadIdx.x;
    int l = t & (LL - 1);
    const float c = -9.210340371976184f / 256.0f;  /* -ln(10000)/256 */
    float div = expf((float)(d & ~1) * c);
    float ang = (float)l * div;
    float pe = (d & 1) ? cosf(ang) : sinf(ang);
    g_H[(size_t)t * DM + d] =
        x[t * 2 + 0] * in_w[d] + x[t * 2 + 1] * in_w[DM + d] + in_b[d] + pe;
}

/* ------------------------------------------------------------------ */
/* block reduce (256 threads): sum + sumsq                             */
/* ------------------------------------------------------------------ */
__device__ __forceinline__ void block_reduce_2(float& s, float& q) {
#pragma unroll
    for (int o = 16; o > 0; o >>= 1) {
        s += __shfl_xor_sync(0xffffffffu, s, o);
        q += __shfl_xor_sync(0xffffffffu, q, o);
    }
    __shared__ float sh[16];
    int w = threadIdx.x >> 5;
    if ((threadIdx.x & 31) == 0) { sh[w] = s; sh[w + 8] = q; }
    __syncthreads();
    float ts = 0.f, tq = 0.f;
#pragma unroll
    for (int i = 0; i < 8; i++) { ts += sh[i]; tq += sh[8 + i]; }
    s = ts; q = tq;
}

/* dst = LN(src) */
__global__ void ln_kernel(const float* __restrict__ src,
                          const float* __restrict__ g,
                          const float* __restrict__ bt,
                          float* __restrict__ dst) {
    int t = blockIdx.x, d = threadIdx.x;
    size_t idx = (size_t)t * DM + d;
    float v = src[idx];
    float s = v, q = v * v;
    block_reduce_2(s, q);
    float mean = s * (1.f / DM);
    float var  = q * (1.f / DM) - mean * mean;
    float r = rsqrtf(var + EPSF);
    dst[idx] = (v - mean) * r * g[d] + bt[d];
}

/* H += LN(P + S) */
__global__ void lna_kernel(const float* __restrict__ Pp,
                           const float* __restrict__ Sp,
                           const float* __restrict__ g,
                           const float* __restrict__ bt,
                           float* __restrict__ H) {
    int t = blockIdx.x, d = threadIdx.x;
    size_t idx = (size_t)t * DM + d;
    float v = Pp[idx] + Sp[idx];
    float s = v, q = v * v;
    block_reduce_2(s, q);
    float mean = s * (1.f / DM);
    float var  = q * (1.f / DM) - mean * mean;
    float r = rsqrtf(var + EPSF);
    H[idx] += (v - mean) * r * g[d] + bt[d];
}

/* ------------------------------------------------------------------ */
/* tiled SGEMM: C[M,N] (=|+=) A[M,K] @ B[K,N] + bias                   */
/* BM=128, BN=64, BK=16, 256 threads, 8x4 per-thread tile              */
/* USEVOL: scale A column k by g_VOL[b*DFF + k] (b = row block / 1024) */
/* ------------------------------------------------------------------ */
template <bool ADD, bool USEVOL>
__global__ void gemm_kernel(const float* __restrict__ A,
                            const float* __restrict__ Bw,
                            const float* __restrict__ bias,
                            float* __restrict__ C,
                            int M, int N, int K) {
    __shared__ float As[16][128];
    __shared__ float Bs[16][64];

    int tid = threadIdx.x;
    int tx = tid & 15;          /* col group 0..15 */
    int ty = tid >> 4;          /* row group 0..15 */
    int bn0 = blockIdx.x * 64;
    int bm0 = blockIdx.y * 128;

    const float* volp = USEVOL ? (g_VOL + (size_t)((bm0 >> 10) << 10)) : (const float*)0;

    float acc[8][4];
#pragma unroll
    for (int i = 0; i < 8; i++)
#pragma unroll
        for (int j = 0; j < 4; j++) acc[i][j] = 0.f;

    int ar = tid >> 1;               /* 0..127 */
    int ac = (tid & 1) * 8;          /* 0 or 8 */
    int br = tid >> 4;               /* 0..15  */
    int bc = (tid & 15) * 4;         /* 0..60  */

    for (int k0 = 0; k0 < K; k0 += 16) {
        float4 a0 = *(const float4*)&A[(size_t)(bm0 + ar) * K + k0 + ac];
        float4 a1 = *(const float4*)&A[(size_t)(bm0 + ar) * K + k0 + ac + 4];
        if (USEVOL) {
            a0.x *= volp[k0 + ac + 0]; a0.y *= volp[k0 + ac + 1];
            a0.z *= volp[k0 + ac + 2]; a0.w *= volp[k0 + ac + 3];
            a1.x *= volp[k0 + ac + 4]; a1.y *= volp[k0 + ac + 5];
            a1.z *= volp[k0 + ac + 6]; a1.w *= volp[k0 + ac + 7];
        }
        As[ac + 0][ar] = a0.x; As[ac + 1][ar] = a0.y;
        As[ac + 2][ar] = a0.z; As[ac + 3][ar] = a0.w;
        As[ac + 4][ar] = a1.x; As[ac + 5][ar] = a1.y;
        As[ac + 6][ar] = a1.z; As[ac + 7][ar] = a1.w;

        float4 bv = *(const float4*)&Bw[(size_t)(k0 + br) * N + bn0 + bc];
        *(float4*)&Bs[br][bc] = bv;

        __syncthreads();
#pragma unroll
        for (int kk = 0; kk < 16; kk++) {
            float a[8], bb[4];
            *(float4*)&a[0] = *(const float4*)&As[kk][ty * 8];
            *(float4*)&a[4] = *(const float4*)&As[kk][ty * 8 + 4];
            *(float4*)&bb[0] = *(const float4*)&Bs[kk][tx * 4];
#pragma unroll
            for (int i = 0; i < 8; i++)
#pragma unroll
                for (int j = 0; j < 4; j++)
                    acc[i][j] += a[i] * bb[j];
        }
        __syncthreads();
    }

#pragma unroll
    for (int i = 0; i < 8; i++) {
        size_t row = (size_t)(bm0 + ty * 8 + i);
#pragma unroll
        for (int j = 0; j < 4; j++) {
            int col = bn0 + tx * 4 + j;
            float r = acc[i][j] + bias[col];
            if (ADD) C[row * N + col] += r;
            else     C[row * N + col] = r;
        }
    }
}

/* ------------------------------------------------------------------ */
/* ProbSparse attention: one warp per query row, 8 rows per block      */
/* ------------------------------------------------------------------ */
#define ATTN_SMEM ((8 * 1024 + 128 * 33 + 8 * 256) * 4)

__device__ __forceinline__ unsigned f2u(float f) {
    unsigned u = __float_as_uint(f);
    return (u & 0x80000000u) ? ~u : (u | 0x80000000u);
}

__global__ void attn_kernel(const float* __restrict__ QKV, float* __restrict__ O) {
    extern __shared__ float smx[];
    float* sc = smx;                           /* 8 x 1024 scores      */
    float* kv = smx + 8 * 1024;                /* 128 x 33 K/V tile    */
    int* hist = (int*)(smx + 8 * 1024 + 128 * 33); /* 8 x 256 bins     */

    int tid  = threadIdx.x;
    int lane = tid & 31;
    int w    = tid >> 5;
    int bh = blockIdx.y;
    int b = bh >> 3, h = bh & 7;
    int q = blockIdx.x * 8 + w;
    size_t tokbase = (size_t)b * LL;

    /* q row into registers (broadcast load per warp) */
    float qr[32];
    {
        const float* qp = QKV + (tokbase + q) * 768 + h * 32;
#pragma unroll
        for (int i = 0; i < 32; i++) qr[i] = qp[i];
    }
    const float scale = 0.17677669529663687f; /* 1/sqrt(32) */
    float lmax = -1e30f;
    float* scw = sc + w * 1024;

    /* phase 1: scores */
    for (int kt = 0; kt < 8; kt++) {
        {   /* cooperative K-tile load: 128 keys x 32 dims */
            int key = tid >> 1;
            int dd = (tid & 1) * 16;
            const float* kp = QKV + (tokbase + kt * 128 + key) * 768 + 256 + h * 32 + dd;
            float* dst = kv + key * 33 + dd;
#pragma unroll
            for (int i = 0; i < 4; i++) {
                float4 v = *(const float4*)(kp + 4 * i);
                dst[4 * i + 0] = v.x; dst[4 * i + 1] = v.y;
                dst[4 * i + 2] = v.z; dst[4 * i + 3] = v.w;
            }
        }
        __syncthreads();
        float a0 = 0.f, a1 = 0.f, a2 = 0.f, a3 = 0.f;
        const float* kb = kv + lane * 33;
#pragma unroll
        for (int d = 0; d < 32; d++) {
            float qv = qr[d];
            a0 += qv * kb[d];
            a1 += qv * kb[32 * 33 + d];
            a2 += qv * kb[64 * 33 + d];
            a3 += qv * kb[96 * 33 + d];
        }
        a0 *= scale; a1 *= scale; a2 *= scale; a3 *= scale;
        scw[kt * 128 + lane     ] = a0;
        scw[kt * 128 + lane + 32] = a1;
        scw[kt * 128 + lane + 64] = a2;
        scw[kt * 128 + lane + 96] = a3;
        lmax = fmaxf(lmax, fmaxf(fmaxf(a0, a1), fmaxf(a2, a3)));
        __syncthreads();
    }
#pragma unroll
    for (int o = 16; o > 0; o >>= 1)
        lmax = fmaxf(lmax, __shfl_xor_sync(0xffffffffu, lmax, o));

    /* phase 2: exact 256-th largest via 4-pass radix select on u32 bits */
    int* hw = hist + w * 256;
    unsigned prefix = 0;
    int krem = TOPK;
#pragma unroll
    for (int pass = 0; pass < 4; pass++) {
        int shift = 24 - 8 * pass;
        for (int i = lane; i < 256; i += 32) hw[i] = 0;
        __syncwarp();
        for (int j = lane; j < 1024; j += 32) {
            unsigned u = f2u(scw[j]);
            /* prefix match on bytes above current one (UB-safe double shift) */
            bool ok = ((u >> shift) >> 8) == ((prefix >> shift) >> 8);
            if (ok) atomicAdd(&hw[(u >> shift) & 255], 1);
        }
        __syncwarp();
        int selbin = 0, knew = 0;
        if (lane == 0) {
            int c = 0, bn;
            for (bn = 255; bn >= 0; --bn) {
                c += hw[bn];
                if (c >= krem) break;
            }
            if (bn < 0) bn = 0;
            knew = krem - (c - hw[bn]);
            selbin = bn;
        }
        selbin = __shfl_sync(0xffffffffu, selbin, 0);
        krem   = __shfl_sync(0xffffffffu, knew, 0);
        prefix |= ((unsigned)selbin) << shift;
        __syncwarp();
    }
    unsigned thr = prefix;

    /* masked softmax weights written back into score row */
    float zs = 0.f;
    for (int j = lane; j < 1024; j += 32) {
        float s = scw[j];
        float wt = (f2u(s) >= thr) ? expf(s - lmax) : 0.f;
        scw[j] = wt;
        zs += wt;
    }
#pragma unroll
    for (int o = 16; o > 0; o >>= 1) zs += __shfl_xor_sync(0xffffffffu, zs, o);
    float rz = 1.f / zs;

    /* phase 3: O = attn @ V (75% of weights are exactly 0 -> skip)     */
    float oacc = 0.f;
    for (int kt = 0; kt < 8; kt++) {
        __syncthreads();
        {
            int key = tid >> 1;
            int dd = (tid & 1) * 16;
            const float* vp = QKV + (tokbase + kt * 128 + key) * 768 + 512 + h * 32 + dd;
            float* dst = kv + key * 33 + dd;
#pragma unroll
            for (int i = 0; i < 4; i++) {
                float4 v = *(const float4*)(vp + 4 * i);
                dst[4 * i + 0] = v.x; dst[4 * i + 1] = v.y;
                dst[4 * i + 2] = v.z; dst[4 * i + 3] = v.w;
            }
        }
        __syncthreads();
        const float* vb = kv + lane;
        const float* ws = scw + kt * 128;
        for (int j = 0; j < 128; j++) {
            float wj = ws[j];                 /* uniform across warp */
            if (wj != 0.f) oacc += wj * vb[j * 33];
        }
    }
    O[(tokbase + q) * 256 + h * 32 + lane] = oacc * rz;
}

/* ------------------------------------------------------------------ */
/* Volatilite: vol[b,j] = std over L of F[b,:,j]                       */
/* ------------------------------------------------------------------ */
__global__ void vol_kernel(const float* __restrict__ F) {
    int tx = threadIdx.x & 127;
    int ty = threadIdx.x >> 7;        /* 0..3 */
    int j = blockIdx.x * 128 + tx;
    int b = blockIdx.y;
    float s = 0.f, ss = 0.f;
    for (int l = ty; l < LL; l += 4) {
        float v = F[((size_t)(b * LL + l)) * DFF + j];
        s += v; ss += v * v;
    }
    __shared__ float sh1[4][128], sh2[4][128];
    sh1[ty][tx] = s; sh2[ty][tx] = ss;
    __syncthreads();
    if (ty == 0) {
        s  = sh1[0][tx] + sh1[1][tx] + sh1[2][tx] + sh1[3][tx];
        ss = sh2[0][tx] + sh2[1][tx] + sh2[2][tx] + sh2[3][tx];
        float mean = s * (1.f / LL);
        float var  = ss * (1.f / LL) - mean * mean;
        g_VOL[b * DFF + j] = sqrtf(fmaxf(var, 0.f));
    }
}

/* ------------------------------------------------------------------ */
extern "C" void kernel_launch(void* const* d_in, const int* in_sizes, int n_in,
                              void* d_out, int out_size) {
    const float* x     = (const float*)d_in[0];
    const float* in_w  = (const float*)d_in[1];
    const float* in_b  = (const float*)d_in[2];
    const float* ln1_g = (const float*)d_in[3];
    const float* ln1_b = (const float*)d_in[4];
    const float* qkv_w = (const float*)d_in[5];
    const float* qkv_b = (const float*)d_in[6];
    const float* out_w = (const float*)d_in[7];
    const float* out_b = (const float*)d_in[8];
    const float* lna_g = (const float*)d_in[9];
    const float* lna_b = (const float*)d_in[10];
    const float* ln2_g = (const float*)d_in[11];
    const float* ln2_b = (const float*)d_in[12];
    const float* ff1_w = (const float*)d_in[13];
    const float* ff1_b = (const float*)d_in[14];
    const float* ff2_w = (const float*)d_in[15];
    const float* ff2_b = (const float*)d_in[16];
    const float* lnf_g = (const float*)d_in[17];
    const float* lnf_b = (const float*)d_in[18];
    float* out = (float*)d_out;

    float *H, *S, *Q, *O, *P, *F;
    cudaGetSymbolAddress((void**)&H, g_H);
    cudaGetSymbolAddress((void**)&S, g_S);
    cudaGetSymbolAddress((void**)&Q, g_QKV);
    cudaGetSymbolAddress((void**)&O, g_O);
    cudaGetSymbolAddress((void**)&P, g_P);
    cudaGetSymbolAddress((void**)&F, g_F);

    cudaFuncSetAttribute((const void*)attn_kernel,
                         cudaFuncAttributeMaxDynamicSharedMemorySize, ATTN_SMEM);

    embed_kernel<<<TT, 256>>>(x, in_w, in_b);

    for (int layer = 0; layer < NLAY; layer++) {
        /* s2 = LN1(h) */
        ln_kernel<<<TT, 256>>>(H, ln1_g, ln1_b, S);
        /* qkv = s2 @ qkv_w + qkv_b */
        gemm_kernel<false, false><<<dim3(768 / 64, TT / 128), 256>>>(
            S, qkv_w, qkv_b, Q, TT, 768, DM);
        /* probsparse attention */
        attn_kernel<<<dim3(LL / 8, BB * NH), 256, ATTN_SMEM>>>(Q, O);
        /* P = O @ out_w + out_b */
        gemm_kernel<false, false><<<dim3(256 / 64, TT / 128), 256>>>(
            O, out_w, out_b, P, TT, DM, DM);
        /* h += LN(P + s2) */
        lna_kernel<<<TT, 256>>>(P, S, lna_g, lna_b, H);
        /* s2 = LN2(h) */
        ln_kernel<<<TT, 256>>>(H, ln2_g, ln2_b, S);
        /* F = s2 @ ff1_w + ff1_b */
        gemm_kernel<false, false><<<dim3(1024 / 64, TT / 128), 256>>>(
            S, ff1_w, ff1_b, F, TT, DFF, DM);
        /* vol[b,j] */
        vol_kernel<<<dim3(DFF / 128, BB), 512>>>(F);
        /* h += (F * vol) @ ff2_w + ff2_b */
        gemm_kernel<true, true><<<dim3(256 / 64, TT / 128), 256>>>(
            F, ff2_w, ff2_b, H, TT, DM, DFF);
    }

    /* out = LN_f(h) */
    ln_kernel<<<TT, 256>>>(H, lnf_g, lnf_b, out);
}

// round 2
// speedup vs baseline: 1.1481x; 1.1481x over previous
#include <cuda_runtime.h>
#include <math.h>

#define DM   256
#define NH   8
#define DK   32
#define DFF  1024
#define NLAY 6
#define BB   8
#define LL   1024
#define TT   (BB * LL)     /* 8192 tokens */
#define TOPK 256
#define EPSF 1e-5f

/* ------------------------------------------------------------------ */
/* scratch (static device globals: no runtime allocation)             */
/* ------------------------------------------------------------------ */
__device__ float g_H[TT * DM];
__device__ float g_S[TT * DM];
__device__ float g_QKV[TT * 3 * DM];
__device__ float g_O[TT * DM];
__device__ float g_P[TT * DM];
__device__ float g_F[TT * DFF];
__device__ float g_VOL[BB * DFF];

/* ------------------------------------------------------------------ */
/* embed: h = x @ in_w + in_b + PE                                     */
/* ------------------------------------------------------------------ */
__global__ void embed_kernel(const float* __restrict__ x,
                             const float* __restrict__ in_w,
                             const float* __restrict__ in_b) {
    int t = blockIdx.x;
    int d = threadIdx.x;
    int l = t & (LL - 1);
    const float c = -9.210340371976184f / 256.0f;  /* -ln(10000)/256 */
    float div = expf((float)(d & ~1) * c);
    float ang = (float)l * div;
    float pe = (d & 1) ? cosf(ang) : sinf(ang);
    g_H[(size_t)t * DM + d] =
        x[t * 2 + 0] * in_w[d] + x[t * 2 + 1] * in_w[DM + d] + in_b[d] + pe;
}

/* ------------------------------------------------------------------ */
/* block reduce (256 threads): sum + sumsq                             */
/* ------------------------------------------------------------------ */
__device__ __forceinline__ void block_reduce_2(float& s, float& q) {
#pragma unroll
    for (int o = 16; o > 0; o >>= 1) {
        s += __shfl_xor_sync(0xffffffffu, s, o);
        q += __shfl_xor_sync(0xffffffffu, q, o);
    }
    __shared__ float sh[16];
    int w = threadIdx.x >> 5;
    if ((threadIdx.x & 31) == 0) { sh[w] = s; sh[w + 8] = q; }
    __syncthreads();
    float ts = 0.f, tq = 0.f;
#pragma unroll
    for (int i = 0; i < 8; i++) { ts += sh[i]; tq += sh[8 + i]; }
    s = ts; q = tq;
}

/* dst = LN(src) */
__global__ void ln_kernel(const float* __restrict__ src,
                          const float* __restrict__ g,
                          const float* __restrict__ bt,
                          float* __restrict__ dst) {
    int t = blockIdx.x, d = threadIdx.x;
    size_t idx = (size_t)t * DM + d;
    float v = src[idx];
    float s = v, q = v * v;
    block_reduce_2(s, q);
    float mean = s * (1.f / DM);
    float var  = q * (1.f / DM) - mean * mean;
    float r = rsqrtf(var + EPSF);
    dst[idx] = (v - mean) * r * g[d] + bt[d];
}

/* H += LN(P + S) */
__global__ void lna_kernel(const float* __restrict__ Pp,
                           const float* __restrict__ Sp,
                           const float* __restrict__ g,
                           const float* __restrict__ bt,
                           float* __restrict__ H) {
    int t = blockIdx.x, d = threadIdx.x;
    size_t idx = (size_t)t * DM + d;
    float v = Pp[idx] + Sp[idx];
    float s = v, q = v * v;
    block_reduce_2(s, q);
    float mean = s * (1.f / DM);
    float var  = q * (1.f / DM) - mean * mean;
    float r = rsqrtf(var + EPSF);
    H[idx] += (v - mean) * r * g[d] + bt[d];
}

/* ------------------------------------------------------------------ */
/* tiled SGEMM: C[M,N] (=|+=) A[M,K] @ B[K,N] + bias                   */
/* BM=128, BN=128, BK=16, 256 threads, 8x8 per-thread tile             */
/* USEVOL: scale A column k by g_VOL[b*DFF + k] (b = row block / 1024) */
/* ------------------------------------------------------------------ */
template <bool ADD, bool USEVOL>
__global__ void gemm_kernel(const float* __restrict__ A,
                            const float* __restrict__ Bw,
                            const float* __restrict__ bias,
                            float* __restrict__ C,
                            int M, int N, int K) {
    __shared__ float As[16][128];
    __shared__ float Bs[16][128];

    int tid = threadIdx.x;
    int tx = tid & 15;          /* col group 0..15 */
    int ty = tid >> 4;          /* row group 0..15 */
    int bn0 = blockIdx.x * 128;
    int bm0 = blockIdx.y * 128;

    const float* volp = USEVOL ? (g_VOL + (size_t)((bm0 >> 10) << 10)) : (const float*)0;

    float acc[8][8];
#pragma unroll
    for (int i = 0; i < 8; i++)
#pragma unroll
        for (int j = 0; j < 8; j++) acc[i][j] = 0.f;

    int ar = tid >> 1;               /* 0..127 */
    int ac = (tid & 1) * 8;          /* 0 or 8 */
    int br = tid >> 4;               /* 0..15  */
    int bc = (tid & 15) * 8;         /* 0..120 */

    for (int k0 = 0; k0 < K; k0 += 16) {
        float4 a0 = *(const float4*)&A[(size_t)(bm0 + ar) * K + k0 + ac];
        float4 a1 = *(const float4*)&A[(size_t)(bm0 + ar) * K + k0 + ac + 4];
        if (USEVOL) {
            a0.x *= volp[k0 + ac + 0]; a0.y *= volp[k0 + ac + 1];
            a0.z *= volp[k0 + ac + 2]; a0.w *= volp[k0 + ac + 3];
            a1.x *= volp[k0 + ac + 4]; a1.y *= volp[k0 + ac + 5];
            a1.z *= volp[k0 + ac + 6]; a1.w *= volp[k0 + ac + 7];
        }
        As[ac + 0][ar] = a0.x; As[ac + 1][ar] = a0.y;
        As[ac + 2][ar] = a0.z; As[ac + 3][ar] = a0.w;
        As[ac + 4][ar] = a1.x; As[ac + 5][ar] = a1.y;
        As[ac + 6][ar] = a1.z; As[ac + 7][ar] = a1.w;

        float4 b0 = *(const float4*)&Bw[(size_t)(k0 + br) * N + bn0 + bc];
        float4 b1 = *(const float4*)&Bw[(size_t)(k0 + br) * N + bn0 + bc + 4];
        *(float4*)&Bs[br][bc]     = b0;
        *(float4*)&Bs[br][bc + 4] = b1;

        __syncthreads();
#pragma unroll
        for (int kk = 0; kk < 16; kk++) {
            float a[8], bb[8];
            *(float4*)&a[0]  = *(const float4*)&As[kk][ty * 8];
            *(float4*)&a[4]  = *(const float4*)&As[kk][ty * 8 + 4];
            *(float4*)&bb[0] = *(const float4*)&Bs[kk][tx * 8];
            *(float4*)&bb[4] = *(const float4*)&Bs[kk][tx * 8 + 4];
#pragma unroll
            for (int i = 0; i < 8; i++)
#pragma unroll
                for (int j = 0; j < 8; j++)
                    acc[i][j] += a[i] * bb[j];
        }
        __syncthreads();
    }

    float bia[8];
    *(float4*)&bia[0] = *(const float4*)&bias[bn0 + tx * 8];
    *(float4*)&bia[4] = *(const float4*)&bias[bn0 + tx * 8 + 4];

#pragma unroll
    for (int i = 0; i < 8; i++) {
        size_t row = (size_t)(bm0 + ty * 8 + i);
        float* cp = &C[row * N + bn0 + tx * 8];
        if (ADD) {
            float4 c0 = *(float4*)&cp[0];
            float4 c1 = *(float4*)&cp[4];
            c0.x += acc[i][0] + bia[0]; c0.y += acc[i][1] + bia[1];
            c0.z += acc[i][2] + bia[2]; c0.w += acc[i][3] + bia[3];
            c1.x += acc[i][4] + bia[4]; c1.y += acc[i][5] + bia[5];
            c1.z += acc[i][6] + bia[6]; c1.w += acc[i][7] + bia[7];
            *(float4*)&cp[0] = c0; *(float4*)&cp[4] = c1;
        } else {
            float4 c0, c1;
            c0.x = acc[i][0] + bia[0]; c0.y = acc[i][1] + bia[1];
            c0.z = acc[i][2] + bia[2]; c0.w = acc[i][3] + bia[3];
            c1.x = acc[i][4] + bia[4]; c1.y = acc[i][5] + bia[5];
            c1.z = acc[i][6] + bia[6]; c1.w = acc[i][7] + bia[7];
            *(float4*)&cp[0] = c0; *(float4*)&cp[4] = c1;
        }
    }
}

/* ------------------------------------------------------------------ */
/* ProbSparse attention: one warp per query row, 16 rows per block     */
/* smem: scores 16x1024 | kbuf (K pitch-36 / V^T pitch-132) | hist     */
/* ------------------------------------------------------------------ */
#define AT_WARPS 16
#define AT_THREADS 512
#define SC_FLOATS (AT_WARPS * 1024)
#define KBUF_FLOATS (128 * 36)          /* >= 32*132 = 4224 */
#define ATTN_SMEM ((SC_FLOATS + KBUF_FLOATS + AT_WARPS * 256) * 4)

__device__ __forceinline__ unsigned f2u(float f) {
    unsigned u = __float_as_uint(f);
    return (u & 0x80000000u) ? ~u : (u | 0x80000000u);
}

__global__ void attn_kernel(const float* __restrict__ QKV, float* __restrict__ O) {
    extern __shared__ float smx[];
    float* sc   = smx;                              /* 16 x 1024 scores */
    float* kbuf = smx + SC_FLOATS;                  /* K / V^T tile     */
    int*   hist = (int*)(smx + SC_FLOATS + KBUF_FLOATS);

    int tid  = threadIdx.x;
    int lane = tid & 31;
    int w    = tid >> 5;
    int bh = blockIdx.y;
    int b = bh >> 3, h = bh & 7;
    int q = blockIdx.x * AT_WARPS + w;
    size_t tokbase = (size_t)b * LL;

    /* q row into registers as 8 float4 */
    float4 qr[8];
    {
        const float4* qp = (const float4*)(QKV + (tokbase + q) * 768 + h * 32);
#pragma unroll
        for (int i = 0; i < 8; i++) qr[i] = qp[i];
    }
    const float scale = 0.17677669529663687f; /* 1/sqrt(32) */
    float lmax = -1e30f;
    float* scw = sc + w * 1024;

    /* ---------------- phase 1: scores ---------------- */
    for (int kt = 0; kt < 8; kt++) {
        /* cooperative K-tile load: 128 keys x 32 dims, pitch 36 */
#pragma unroll
        for (int rep = 0; rep < 2; rep++) {
            int idx = tid + rep * AT_THREADS;      /* 0..1023 */
            int key = idx >> 3;
            int dd  = (idx & 7) * 4;
            float4 v = *(const float4*)(QKV +
                (tokbase + kt * 128 + key) * 768 + 256 + h * 32 + dd);
            *(float4*)&kbuf[key * 36 + dd] = v;
        }
        __syncthreads();

#pragma unroll
        for (int kk = 0; kk < 4; kk++) {
            const float4* kb = (const float4*)&kbuf[(lane + kk * 32) * 36];
            float s = 0.f;
#pragma unroll
            for (int i = 0; i < 8; i++) {
                float4 kv = kb[i];
                s += qr[i].x * kv.x + qr[i].y * kv.y
                   + qr[i].z * kv.z + qr[i].w * kv.w;
            }
            s *= scale;
            scw[kt * 128 + kk * 32 + lane] = s;
            lmax = fmaxf(lmax, s);
        }
        __syncthreads();
    }
#pragma unroll
    for (int o = 16; o > 0; o >>= 1)
        lmax = fmaxf(lmax, __shfl_xor_sync(0xffffffffu, lmax, o));

    /* -------- phase 2: exact 256-th largest (4-pass radix) -------- */
    int* hw = hist + w * 256;
    unsigned prefix = 0;
    int krem = TOPK;
#pragma unroll
    for (int pass = 0; pass < 4; pass++) {
        int shift = 24 - 8 * pass;
        for (int i = lane; i < 256; i += 32) hw[i] = 0;
        __syncwarp();
        for (int j4 = lane; j4 < 256; j4 += 32) {
            float4 s4 = ((const float4*)scw)[j4];
            float sv[4] = {s4.x, s4.y, s4.z, s4.w};
#pragma unroll
            for (int e = 0; e < 4; e++) {
                unsigned u = f2u(sv[e]);
                bool ok = ((u >> shift) >> 8) == ((prefix >> shift) >> 8);
                if (ok) atomicAdd(&hw[(u >> shift) & 255], 1);
            }
        }
        __syncwarp();
        int selbin = 0, knew = 0;
        if (lane == 0) {
            int c = 0, bn;
            for (bn = 255; bn >= 0; --bn) {
                c += hw[bn];
                if (c >= krem) break;
            }
            if (bn < 0) bn = 0;
            knew = krem - (c - hw[bn]);
            selbin = bn;
        }
        selbin = __shfl_sync(0xffffffffu, selbin, 0);
        krem   = __shfl_sync(0xffffffffu, knew, 0);
        prefix |= ((unsigned)selbin) << shift;
        __syncwarp();
    }
    unsigned thr = prefix;

    /* masked softmax weights written back into score row */
    float zs = 0.f;
    for (int j4 = lane; j4 < 256; j4 += 32) {
        float4 s4 = ((const float4*)scw)[j4];
        float4 w4;
        w4.x = (f2u(s4.x) >= thr) ? expf(s4.x - lmax) : 0.f;
        w4.y = (f2u(s4.y) >= thr) ? expf(s4.y - lmax) : 0.f;
        w4.z = (f2u(s4.z) >= thr) ? expf(s4.z - lmax) : 0.f;
        w4.w = (f2u(s4.w) >= thr) ? expf(s4.w - lmax) : 0.f;
        ((float4*)scw)[j4] = w4;
        zs += w4.x + w4.y + w4.z + w4.w;
    }
#pragma unroll
    for (int o = 16; o > 0; o >>= 1) zs += __shfl_xor_sync(0xffffffffu, zs, o);
    float rz = 1.f / zs;

    /* -------- phase 3: O = attn @ V (V^T tile, pitch 132) -------- */
    float oacc = 0.f;
    for (int kt = 0; kt < 8; kt++) {
        __syncthreads();
#pragma unroll
        for (int rep = 0; rep < 2; rep++) {
            int idx = tid + rep * AT_THREADS;
            int key = idx & 127;
            int dd  = (idx >> 7) * 4;
            float4 v = *(const float4*)(QKV +
                (tokbase + kt * 128 + key) * 768 + 512 + h * 32 + dd);
            kbuf[(dd + 0) * 132 + key] = v.x;
            kbuf[(dd + 1) * 132 + key] = v.y;
            kbuf[(dd + 2) * 132 + key] = v.z;
            kbuf[(dd + 3) * 132 + key] = v.w;
        }
        __syncthreads();
        const float4* vrow = (const float4*)&kbuf[lane * 132];
        const float4* ws   = (const float4*)(scw + kt * 128);
#pragma unroll 8
        for (int j = 0; j < 32; j++) {
            float4 w4 = ws[j];                 /* uniform across warp */
            if (w4.x != 0.f || w4.y != 0.f || w4.z != 0.f || w4.w != 0.f) {
                float4 v4 = vrow[j];
                oacc += w4.x * v4.x + w4.y * v4.y + w4.z * v4.z + w4.w * v4.w;
            }
        }
    }
    O[(tokbase + q) * 256 + h * 32 + lane] = oacc * rz;
}

/* ------------------------------------------------------------------ */
/* Volatilite: vol[b,j] = std over L of F[b,:,j]                       */
/* ------------------------------------------------------------------ */
__global__ void vol_kernel(const float* __restrict__ F) {
    int tx = threadIdx.x & 127;
    int ty = threadIdx.x >> 7;        /* 0..3 */
    int j = blockIdx.x * 128 + tx;
    int b = blockIdx.y;
    float s = 0.f, ss = 0.f;
    for (int l = ty; l < LL; l += 4) {
        float v = F[((size_t)(b * LL + l)) * DFF + j];
        s += v; ss += v * v;
    }
    __shared__ float sh1[4][128], sh2[4][128];
    sh1[ty][tx] = s; sh2[ty][tx] = ss;
    __syncthreads();
    if (ty == 0) {
        s  = sh1[0][tx] + sh1[1][tx] + sh1[2][tx] + sh1[3][tx];
        ss = sh2[0][tx] + sh2[1][tx] + sh2[2][tx] + sh2[3][tx];
        float mean = s * (1.f / LL);
        float var  = ss * (1.f / LL) - mean * mean;
        g_VOL[b * DFF + j] = sqrtf(fmaxf(var, 0.f));
    }
}

/* ------------------------------------------------------------------ */
extern "C" void kernel_launch(void* const* d_in, const int* in_sizes, int n_in,
                              void* d_out, int out_size) {
    const float* x     = (const float*)d_in[0];
    const float* in_w  = (const float*)d_in[1];
    const float* in_b  = (const float*)d_in[2];
    const float* ln1_g = (const float*)d_in[3];
    const float* ln1_b = (const float*)d_in[4];
    const float* qkv_w = (const float*)d_in[5];
    const float* qkv_b = (const float*)d_in[6];
    const float* out_w = (const float*)d_in[7];
    const float* out_b = (const float*)d_in[8];
    const float* lna_g = (const float*)d_in[9];
    const float* lna_b = (const float*)d_in[10];
    const float* ln2_g = (const float*)d_in[11];
    const float* ln2_b = (const float*)d_in[12];
    const float* ff1_w = (const float*)d_in[13];
    const float* ff1_b = (const float*)d_in[14];
    const float* ff2_w = (const float*)d_in[15];
    const float* ff2_b = (const float*)d_in[16];
    const float* lnf_g = (const float*)d_in[17];
    const float* lnf_b = (const float*)d_in[18];
    float* out = (float*)d_out;

    float *H, *S, *Q, *O, *P, *F;
    cudaGetSymbolAddress((void**)&H, g_H);
    cudaGetSymbolAddress((void**)&S, g_S);
    cudaGetSymbolAddress((void**)&Q, g_QKV);
    cudaGetSymbolAddress((void**)&O, g_O);
    cudaGetSymbolAddress((void**)&P, g_P);
    cudaGetSymbolAddress((void**)&F, g_F);

    cudaFuncSetAttribute((const void*)attn_kernel,
                         cudaFuncAttributeMaxDynamicSharedMemorySize, ATTN_SMEM);

    embed_kernel<<<TT, 256>>>(x, in_w, in_b);

    for (int layer = 0; layer < NLAY; layer++) {
        /* s2 = LN1(h) */
        ln_kernel<<<TT, 256>>>(H, ln1_g, ln1_b, S);
        /* qkv = s2 @ qkv_w + qkv_b */
        gemm_kernel<false, false><<<dim3(768 / 128, TT / 128), 256>>>(
            S, qkv_w, qkv_b, Q, TT, 768, DM);
        /* probsparse attention */
        attn_kernel<<<dim3(LL / AT_WARPS, BB * NH), AT_THREADS, ATTN_SMEM>>>(Q, O);
        /* P = O @ out_w + out_b */
        gemm_kernel<false, false><<<dim3(256 / 128, TT / 128), 256>>>(
            O, out_w, out_b, P, TT, DM, DM);
        /* h += LN(P + s2) */
        lna_kernel<<<TT, 256>>>(P, S, lna_g, lna_b, H);
        /* s2 = LN2(h) */
        ln_kernel<<<TT, 256>>>(H, ln2_g, ln2_b, S);
        /* F = s2 @ ff1_w + ff1_b */
        gemm_kernel<false, false><<<dim3(1024 / 128, TT / 128), 256>>>(
            S, ff1_w, ff1_b, F, TT, DFF, DM);
        /* vol[b,j] */
        vol_kernel<<<dim3(DFF / 128, BB), 512>>>(F);
        /* h += (F * vol) @ ff2_w + ff2_b */
        gemm_kernel<true, true><<<dim3(256 / 128, TT / 128), 256>>>(
            F, ff2_w, ff2_b, H, TT, DM, DFF);
    }

    /* out = LN_f(h) */
    ln_kernel<<<TT, 256>>>(H, lnf_g, lnf_b, out);
}

// round 3
// speedup vs baseline: 1.5138x; 1.3185x over previous
#include <cuda_runtime.h>
#include <math.h>

#define DM   256
#define NH   8
#define DK   32
#define DFF  1024
#define NLAY 6
#define BB   8
#define LL   1024
#define TT   (BB * LL)     /* 8192 tokens */
#define TOPK 256
#define EPSF 1e-5f

/* ------------------------------------------------------------------ */
/* scratch (static device globals: no runtime allocation)             */
/* ------------------------------------------------------------------ */
__device__ float g_H[TT * DM];
__device__ float g_S[TT * DM];
__device__ float g_QKV[TT * 3 * DM];
__device__ float g_O[TT * DM];
__device__ float g_P[TT * DM];
__device__ float g_F[TT * DFF];
__device__ float g_VOL[BB * DFF];

/* ------------------------------------------------------------------ */
/* embed: h = x @ in_w + in_b + PE                                     */
/* ------------------------------------------------------------------ */
__global__ void embed_kernel(const float* __restrict__ x,
                             const float* __restrict__ in_w,
                             const float* __restrict__ in_b) {
    int t = blockIdx.x;
    int d = threadIdx.x;
    int l = t & (LL - 1);
    const float c = -9.210340371976184f / 256.0f;  /* -ln(10000)/256 */
    float div = expf((float)(d & ~1) * c);
    float ang = (float)l * div;
    float pe = (d & 1) ? cosf(ang) : sinf(ang);
    g_H[(size_t)t * DM + d] =
        x[t * 2 + 0] * in_w[d] + x[t * 2 + 1] * in_w[DM + d] + in_b[d] + pe;
}

/* ------------------------------------------------------------------ */
/* LayerNorm: warp per token, 8 tokens per 256-thread block            */
/* ------------------------------------------------------------------ */
__device__ __forceinline__ void warp_reduce_2(float& s, float& q) {
#pragma unroll
    for (int o = 16; o > 0; o >>= 1) {
        s += __shfl_xor_sync(0xffffffffu, s, o);
        q += __shfl_xor_sync(0xffffffffu, q, o);
    }
}

__device__ __forceinline__ float4 ln_apply(float4 v, float mean, float r,
                                           float4 g, float4 b) {
    float4 o;
    o.x = (v.x - mean) * r * g.x + b.x;
    o.y = (v.y - mean) * r * g.y + b.y;
    o.z = (v.z - mean) * r * g.z + b.z;
    o.w = (v.w - mean) * r * g.w + b.w;
    return o;
}

/* dst = LN(src) */
__global__ void ln_kernel(const float* __restrict__ src,
                          const float* __restrict__ g,
                          const float* __restrict__ bt,
                          float* __restrict__ dst) {
    int w = threadIdx.x >> 5, lane = threadIdx.x & 31;
    size_t t = (size_t)blockIdx.x * 8 + w;
    const float4* s4 = (const float4*)(src + t * DM);
    float4 a = s4[lane * 2], b = s4[lane * 2 + 1];
    float s = a.x + a.y + a.z + a.w + b.x + b.y + b.z + b.w;
    float q = a.x*a.x + a.y*a.y + a.z*a.z + a.w*a.w
            + b.x*b.x + b.y*b.y + b.z*b.z + b.w*b.w;
    warp_reduce_2(s, q);
    float mean = s * (1.f / DM);
    float var  = q * (1.f / DM) - mean * mean;
    float r = rsqrtf(var + EPSF);
    float4 g0 = ((const float4*)g)[lane * 2], g1 = ((const float4*)g)[lane * 2 + 1];
    float4 b0 = ((const float4*)bt)[lane * 2], b1 = ((const float4*)bt)[lane * 2 + 1];
    float4* d4 = (float4*)(dst + t * DM);
    d4[lane * 2]     = ln_apply(a, mean, r, g0, b0);
    d4[lane * 2 + 1] = ln_apply(b, mean, r, g1, b1);
}

/* H += LN(P + S) */
__global__ void lna_kernel(const float* __restrict__ Pp,
                           const float* __restrict__ Sp,
                           const float* __restrict__ g,
                           const float* __restrict__ bt,
                           float* __restrict__ H) {
    int w = threadIdx.x >> 5, lane = threadIdx.x & 31;
    size_t t = (size_t)blockIdx.x * 8 + w;
    const float4* p4 = (const float4*)(Pp + t * DM);
    const float4* s4 = (const float4*)(Sp + t * DM);
    float4 pa = p4[lane * 2], pb = p4[lane * 2 + 1];
    float4 sa = s4[lane * 2], sb = s4[lane * 2 + 1];
    float4 a, b;
    a.x = pa.x + sa.x; a.y = pa.y + sa.y; a.z = pa.z + sa.z; a.w = pa.w + sa.w;
    b.x = pb.x + sb.x; b.y = pb.y + sb.y; b.z = pb.z + sb.z; b.w = pb.w + sb.w;
    float s = a.x + a.y + a.z + a.w + b.x + b.y + b.z + b.w;
    float q = a.x*a.x + a.y*a.y + a.z*a.z + a.w*a.w
            + b.x*b.x + b.y*b.y + b.z*b.z + b.w*b.w;
    warp_reduce_2(s, q);
    float mean = s * (1.f / DM);
    float var  = q * (1.f / DM) - mean * mean;
    float r = rsqrtf(var + EPSF);
    float4 g0 = ((const float4*)g)[lane * 2], g1 = ((const float4*)g)[lane * 2 + 1];
    float4 b0 = ((const float4*)bt)[lane * 2], b1 = ((const float4*)bt)[lane * 2 + 1];
    float4 r0 = ln_apply(a, mean, r, g0, b0);
    float4 r1 = ln_apply(b, mean, r, g1, b1);
    float4* h4 = (float4*)(H + t * DM);
    float4 h0 = h4[lane * 2], h1 = h4[lane * 2 + 1];
    h0.x += r0.x; h0.y += r0.y; h0.z += r0.z; h0.w += r0.w;
    h1.x += r1.x; h1.y += r1.y; h1.z += r1.z; h1.w += r1.w;
    h4[lane * 2]     = h0;
    h4[lane * 2 + 1] = h1;
}

/* ------------------------------------------------------------------ */
/* tiled SGEMM: C[M,N] (=|+=) A[M,K] @ B[K,N] + bias                   */
/* BM=128, BN=128, BK=16, 256 threads, 8x8 per-thread tile             */
/* ------------------------------------------------------------------ */
template <bool ADD, bool USEVOL>
__global__ void gemm_kernel(const float* __restrict__ A,
                            const float* __restrict__ Bw,
                            const float* __restrict__ bias,
                            float* __restrict__ C,
                            int M, int N, int K) {
    __shared__ float As[16][128];
    __shared__ float Bs[16][128];

    int tid = threadIdx.x;
    int tx = tid & 15;
    int ty = tid >> 4;
    int bn0 = blockIdx.x * 128;
    int bm0 = blockIdx.y * 128;

    const float* volp = USEVOL ? (g_VOL + (size_t)((bm0 >> 10) << 10)) : (const float*)0;

    float acc[8][8];
#pragma unroll
    for (int i = 0; i < 8; i++)
#pragma unroll
        for (int j = 0; j < 8; j++) acc[i][j] = 0.f;

    int ar = tid >> 1;
    int ac = (tid & 1) * 8;
    int br = tid >> 4;
    int bc = (tid & 15) * 8;

    for (int k0 = 0; k0 < K; k0 += 16) {
        float4 a0 = *(const float4*)&A[(size_t)(bm0 + ar) * K + k0 + ac];
        float4 a1 = *(const float4*)&A[(size_t)(bm0 + ar) * K + k0 + ac + 4];
        if (USEVOL) {
            a0.x *= volp[k0 + ac + 0]; a0.y *= volp[k0 + ac + 1];
            a0.z *= volp[k0 + ac + 2]; a0.w *= volp[k0 + ac + 3];
            a1.x *= volp[k0 + ac + 4]; a1.y *= volp[k0 + ac + 5];
            a1.z *= volp[k0 + ac + 6]; a1.w *= volp[k0 + ac + 7];
        }
        As[ac + 0][ar] = a0.x; As[ac + 1][ar] = a0.y;
        As[ac + 2][ar] = a0.z; As[ac + 3][ar] = a0.w;
        As[ac + 4][ar] = a1.x; As[ac + 5][ar] = a1.y;
        As[ac + 6][ar] = a1.z; As[ac + 7][ar] = a1.w;

        float4 b0 = *(const float4*)&Bw[(size_t)(k0 + br) * N + bn0 + bc];
        float4 b1 = *(const float4*)&Bw[(size_t)(k0 + br) * N + bn0 + bc + 4];
        *(float4*)&Bs[br][bc]     = b0;
        *(float4*)&Bs[br][bc + 4] = b1;

        __syncthreads();
#pragma unroll
        for (int kk = 0; kk < 16; kk++) {
            float a[8], bb[8];
            *(float4*)&a[0]  = *(const float4*)&As[kk][ty * 8];
            *(float4*)&a[4]  = *(const float4*)&As[kk][ty * 8 + 4];
            *(float4*)&bb[0] = *(const float4*)&Bs[kk][tx * 8];
            *(float4*)&bb[4] = *(const float4*)&Bs[kk][tx * 8 + 4];
#pragma unroll
            for (int i = 0; i < 8; i++)
#pragma unroll
                for (int j = 0; j < 8; j++)
                    acc[i][j] += a[i] * bb[j];
        }
        __syncthreads();
    }

    float bia[8];
    *(float4*)&bia[0] = *(const float4*)&bias[bn0 + tx * 8];
    *(float4*)&bia[4] = *(const float4*)&bias[bn0 + tx * 8 + 4];

#pragma unroll
    for (int i = 0; i < 8; i++) {
        size_t row = (size_t)(bm0 + ty * 8 + i);
        float* cp = &C[row * N + bn0 + tx * 8];
        if (ADD) {
            float4 c0 = *(float4*)&cp[0];
            float4 c1 = *(float4*)&cp[4];
            c0.x += acc[i][0] + bia[0]; c0.y += acc[i][1] + bia[1];
            c0.z += acc[i][2] + bia[2]; c0.w += acc[i][3] + bia[3];
            c1.x += acc[i][4] + bia[4]; c1.y += acc[i][5] + bia[5];
            c1.z += acc[i][6] + bia[6]; c1.w += acc[i][7] + bia[7];
            *(float4*)&cp[0] = c0; *(float4*)&cp[4] = c1;
        } else {
            float4 c0, c1;
            c0.x = acc[i][0] + bia[0]; c0.y = acc[i][1] + bia[1];
            c0.z = acc[i][2] + bia[2]; c0.w = acc[i][3] + bia[3];
            c1.x = acc[i][4] + bia[4]; c1.y = acc[i][5] + bia[5];
            c1.z = acc[i][6] + bia[6]; c1.w = acc[i][7] + bia[7];
            *(float4*)&cp[0] = c0; *(float4*)&cp[4] = c1;
        }
    }
}

/* ------------------------------------------------------------------ */
/* ProbSparse attention, 16 queries per 512-thread block               */
/* smem floats: sc 16384 | kbuf 4608 | Qs 576 | hist/list 4096 | tb 160*/
/* ------------------------------------------------------------------ */
#define SC_OFF    0
#define KBUF_OFF  16384
#define QS_OFF    20992
#define HIST_OFF  21568
#define TB_OFF    25664
#define ATTN_SMEM (25824 * 4)

__device__ __forceinline__ unsigned f2u(float f) {
    unsigned u = __float_as_uint(f);
    return (u & 0x80000000u) ? ~u : (u | 0x80000000u);
}
__device__ __forceinline__ float u2f(unsigned x) {
    unsigned v = (x & 0x80000000u) ? (x ^ 0x80000000u) : ~x;
    return __uint_as_float(v);
}

__global__ void __launch_bounds__(512, 2)
attn_kernel(const float* __restrict__ QKV, float* __restrict__ O) {
    extern __shared__ float smx[];
    float* sc   = smx + SC_OFF;
    float* kbuf = smx + KBUF_OFF;
    float* Qs   = smx + QS_OFF;
    int*   histb = (int*)(smx + HIST_OFF);
    int*   tb    = (int*)(smx + TB_OFF);

    int tid = threadIdx.x, lane = tid & 31, w = tid >> 5;
    int bh = blockIdx.y, b = bh >> 3, h = bh & 7;
    int qbase = blockIdx.x * 16;
    size_t tokbase = (size_t)b * LL;
    const float* base = QKV + tokbase * 768 + h * 32;

    /* stage Q tile: 16 x 32, pitch 36 */
    {
        int q = tid >> 5, d = tid & 31;
        Qs[q * 36 + d] = base[(size_t)(qbase + q) * 768 + d];
    }

    const float scale = 0.17677669529663687f; /* 1/sqrt(32) */
    float* row = sc + w * 1024;
    int group = w >> 2;           /* key subgroup 0..3 within tile */
    int q0 = (w & 3) * 4;         /* this warp scores 4 queries    */

    /* ---------------- phase 1: scores (K rows in registers) -------- */
    for (int kt = 0; kt < 8; kt++) {
        __syncthreads();
        {
            int key = tid >> 2, dp = (tid & 3) * 8;
            const float* src = base + (size_t)(kt * 128 + key) * 768 + 256 + dp;
            float4 v0 = *(const float4*)src;
            float4 v1 = *(const float4*)(src + 4);
            *(float4*)&kbuf[key * 36 + dp]     = v0;
            *(float4*)&kbuf[key * 36 + dp + 4] = v1;
        }
        __syncthreads();
        float4 kr[8];
        const float4* kp = (const float4*)&kbuf[(group * 32 + lane) * 36];
#pragma unroll
        for (int i = 0; i < 8; i++) kr[i] = kp[i];
#pragma unroll
        for (int j = 0; j < 4; j++) {
            const float4* qp = (const float4*)&Qs[(q0 + j) * 36];
            float s = 0.f;
#pragma unroll
            for (int i = 0; i < 8; i++) {
                float4 qv = qp[i];
                s += qv.x * kr[i].x + qv.y * kr[i].y
                   + qv.z * kr[i].z + qv.w * kr[i].w;
            }
            sc[(q0 + j) * 1024 + kt * 128 + group * 32 + lane] = s * scale;
        }
    }
    __syncthreads();

    /* -------- phase 2: exact 256-th largest (4-pass radix) --------- */
    int* hw = histb + w * 256;
    const float4* row4 = (const float4*)row;
    unsigned prefix = 0, umax = 0;
    int krem = TOPK;
#pragma unroll
    for (int pass = 0; pass < 4; pass++) {
        int shift = 24 - 8 * pass;
        for (int i = lane; i < 256; i += 32) hw[i] = 0;
        __syncwarp();
        for (int j4 = lane; j4 < 256; j4 += 32) {
            float4 s4 = row4[j4];
            unsigned u0 = f2u(s4.x), u1 = f2u(s4.y);
            unsigned u2 = f2u(s4.z), u3 = f2u(s4.w);
            if (pass == 0) {
                umax = max(max(umax, u0), max(u1, max(u2, u3)));
                atomicAdd(&hw[u0 >> 24], 1);
                atomicAdd(&hw[u1 >> 24], 1);
                atomicAdd(&hw[u2 >> 24], 1);
                atomicAdd(&hw[u3 >> 24], 1);
            } else {
                unsigned hi = (prefix >> shift) >> 8;
                if (((u0 >> shift) >> 8) == hi) atomicAdd(&hw[(u0 >> shift) & 255], 1);
                if (((u1 >> shift) >> 8) == hi) atomicAdd(&hw[(u1 >> shift) & 255], 1);
                if (((u2 >> shift) >> 8) == hi) atomicAdd(&hw[(u2 >> shift) & 255], 1);
                if (((u3 >> shift) >> 8) == hi) atomicAdd(&hw[(u3 >> shift) & 255], 1);
            }
        }
        __syncwarp();
        /* warp-parallel bin selection (descending suffix counts) */
        int gs = 0;
#pragma unroll
        for (int i = 0; i < 8; i++) gs += hw[255 - (lane * 8 + i)];
        int S = gs;
#pragma unroll
        for (int off = 1; off < 32; off <<= 1) {
            int t2 = __shfl_up_sync(0xffffffffu, S, off);
            if (lane >= off) S += t2;
        }
        unsigned bal = __ballot_sync(0xffffffffu, S >= krem);
        int L = __ffs(bal) - 1;
        int SL  = __shfl_sync(0xffffffffu, S, L);
        int gsL = __shfl_sync(0xffffffffu, gs, L);
        int c = SL - gsL, selbin = 255 - L * 8, knew = krem;
#pragma unroll
        for (int i = 0; i < 8; i++) {
            int bn = 255 - (L * 8 + i);
            int hv = hw[bn];
            c += hv;
            if (c >= krem) { selbin = bn; knew = krem - (c - hv); break; }
        }
        prefix |= ((unsigned)selbin) << shift;
        krem = knew;
    }
#pragma unroll
    for (int o = 16; o > 0; o >>= 1)
        umax = max(umax, __shfl_xor_sync(0xffffffffu, umax, o));
    float lmax = u2f(umax);
    unsigned thr = prefix;

    /* -------- softmax + compaction of selected keys ---------------- */
    unsigned short* lst = (unsigned short*)hw;   /* hist is dead now */
    float zs = 0.f;
    int cnt = 0;
    if (lane == 0) tb[w * 10] = 0;
    unsigned ltm = (1u << lane) - 1u;
    for (int kt = 0; kt < 8; kt++) {
        float4 s4 = row4[kt * 32 + lane];
        bool b0 = f2u(s4.x) >= thr, b1 = f2u(s4.y) >= thr;
        bool b2 = f2u(s4.z) >= thr, b3 = f2u(s4.w) >= thr;
        float w0 = b0 ? expf(s4.x - lmax) : 0.f;
        float w1 = b1 ? expf(s4.y - lmax) : 0.f;
        float w2 = b2 ? expf(s4.z - lmax) : 0.f;
        float w3 = b3 ? expf(s4.w - lmax) : 0.f;
        ((float4*)row)[kt * 32 + lane] = make_float4(w0, w1, w2, w3);
        zs += w0 + w1 + w2 + w3;
        int key0 = kt * 128 + lane * 4;
        unsigned m0 = __ballot_sync(0xffffffffu, b0);
        unsigned m1 = __ballot_sync(0xffffffffu, b1);
        unsigned m2 = __ballot_sync(0xffffffffu, b2);
        unsigned m3 = __ballot_sync(0xffffffffu, b3);
        int c0 = __popc(m0), c1 = __popc(m1), c2 = __popc(m2), c3 = __popc(m3);
        int p0 = cnt + __popc(m0 & ltm);
        int p1 = cnt + c0 + __popc(m1 & ltm);
        int p2 = cnt + c0 + c1 + __popc(m2 & ltm);
        int p3 = cnt + c0 + c1 + c2 + __popc(m3 & ltm);
        if (b0 && p0 < 512) lst[p0] = (unsigned short)(key0);
        if (b1 && p1 < 512) lst[p1] = (unsigned short)(key0 + 1);
        if (b2 && p2 < 512) lst[p2] = (unsigned short)(key0 + 2);
        if (b3 && p3 < 512) lst[p3] = (unsigned short)(key0 + 3);
        cnt += c0 + c1 + c2 + c3;
        if (lane == 0) tb[w * 10 + kt + 1] = min(cnt, 512);
    }
#pragma unroll
    for (int o = 16; o > 0; o >>= 1) zs += __shfl_xor_sync(0xffffffffu, zs, o);
    float rz = 1.f / zs;
    __syncwarp();

    /* -------- phase 3: O = attn @ V over compacted keys ------------ */
    float oacc = 0.f;
    for (int kt = 0; kt < 8; kt++) {
        __syncthreads();
        {
            int key = tid >> 2, dp = (tid & 3) * 8;
            const float* src = base + (size_t)(kt * 128 + key) * 768 + 512 + dp;
            float4 v0 = *(const float4*)src;
            float4 v1 = *(const float4*)(src + 4);
            *(float4*)&kbuf[key * 36 + dp]     = v0;
            *(float4*)&kbuf[key * 36 + dp + 4] = v1;
        }
        __syncthreads();
        int i0 = tb[w * 10 + kt], i1 = tb[w * 10 + kt + 1];
        for (int i = i0; i < i1; i++) {
            int key = lst[i];                         /* broadcast     */
            float wt = row[key];                      /* broadcast     */
            oacc = fmaf(wt, kbuf[(key & 127) * 36 + lane], oacc);
        }
    }
    O[(tokbase + qbase + w) * 256 + h * 32 + lane] = oacc * rz;
}

/* ------------------------------------------------------------------ */
/* Volatilite: vol[b,j] = std over L of F[b,:,j]                       */
/* ------------------------------------------------------------------ */
__global__ void vol_kernel(const float* __restrict__ F) {
    int tx = threadIdx.x & 127;
    int ty = threadIdx.x >> 7;
    int j = blockIdx.x * 128 + tx;
    int b = blockIdx.y;
    float s = 0.f, ss = 0.f;
    for (int l = ty; l < LL; l += 4) {
        float v = F[((size_t)(b * LL + l)) * DFF + j];
        s += v; ss += v * v;
    }
    __shared__ float sh1[4][128], sh2[4][128];
    sh1[ty][tx] = s; sh2[ty][tx] = ss;
    __syncthreads();
    if (ty == 0) {
        s  = sh1[0][tx] + sh1[1][tx] + sh1[2][tx] + sh1[3][tx];
        ss = sh2[0][tx] + sh2[1][tx] + sh2[2][tx] + sh2[3][tx];
        float mean = s * (1.f / LL);
        float var  = ss * (1.f / LL) - mean * mean;
        g_VOL[b * DFF + j] = sqrtf(fmaxf(var, 0.f));
    }
}

/* ------------------------------------------------------------------ */
extern "C" void kernel_launch(void* const* d_in, const int* in_sizes, int n_in,
                              void* d_out, int out_size) {
    const float* x     = (const float*)d_in[0];
    const float* in_w  = (const float*)d_in[1];
    const float* in_b  = (const float*)d_in[2];
    const float* ln1_g = (const float*)d_in[3];
    const float* ln1_b = (const float*)d_in[4];
    const float* qkv_w = (const float*)d_in[5];
    const float* qkv_b = (const float*)d_in[6];
    const float* out_w = (const float*)d_in[7];
    const float* out_b = (const float*)d_in[8];
    const float* lna_g = (const float*)d_in[9];
    const float* lna_b = (const float*)d_in[10];
    const float* ln2_g = (const float*)d_in[11];
    const float* ln2_b = (const float*)d_in[12];
    const float* ff1_w = (const float*)d_in[13];
    const float* ff1_b = (const float*)d_in[14];
    const float* ff2_w = (const float*)d_in[15];
    const float* ff2_b = (const float*)d_in[16];
    const float* lnf_g = (const float*)d_in[17];
    const float* lnf_b = (const float*)d_in[18];
    float* out = (float*)d_out;

    float *H, *S, *Q, *O, *P, *F;
    cudaGetSymbolAddress((void**)&H, g_H);
    cudaGetSymbolAddress((void**)&S, g_S);
    cudaGetSymbolAddress((void**)&Q, g_QKV);
    cudaGetSymbolAddress((void**)&O, g_O);
    cudaGetSymbolAddress((void**)&P, g_P);
    cudaGetSymbolAddress((void**)&F, g_F);

    cudaFuncSetAttribute((const void*)attn_kernel,
                         cudaFuncAttributeMaxDynamicSharedMemorySize, ATTN_SMEM);

    embed_kernel<<<TT, 256>>>(x, in_w, in_b);

    for (int layer = 0; layer < NLAY; layer++) {
        /* s2 = LN1(h) */
        ln_kernel<<<TT / 8, 256>>>(H, ln1_g, ln1_b, S);
        /* qkv = s2 @ qkv_w + qkv_b */
        gemm_kernel<false, false><<<dim3(768 / 128, TT / 128), 256>>>(
            S, qkv_w, qkv_b, Q, TT, 768, DM);
        /* probsparse attention */
        attn_kernel<<<dim3(LL / 16, BB * NH), 512, ATTN_SMEM>>>(Q, O);
        /* P = O @ out_w + out_b */
        gemm_kernel<false, false><<<dim3(256 / 128, TT / 128), 256>>>(
            O, out_w, out_b, P, TT, DM, DM);
        /* h += LN(P + s2) */
        lna_kernel<<<TT / 8, 256>>>(P, S, lna_g, lna_b, H);
        /* s2 = LN2(h) */
        ln_kernel<<<TT / 8, 256>>>(H, ln2_g, ln2_b, S);
        /* F = s2 @ ff1_w + ff1_b */
        gemm_kernel<false, false><<<dim3(1024 / 128, TT / 128), 256>>>(
            S, ff1_w, ff1_b, F, TT, DFF, DM);
        /* vol[b,j] */
        vol_kernel<<<dim3(DFF / 128, BB), 512>>>(F);
        /* h += (F * vol) @ ff2_w + ff2_b */
        gemm_kernel<true, true><<<dim3(256 / 128, TT / 128), 256>>>(
            F, ff2_w, ff2_b, H, TT, DM, DFF);
    }

    /* out = LN_f(h) */
    ln_kernel<<<TT / 8, 256>>>(H, lnf_g, lnf_b, out);
}

// round 4
// speedup vs baseline: 1.5853x; 1.0472x over previous
#include <cuda_runtime.h>
#include <math.h>

#define DM   256
#define NH   8
#define DK   32
#define DFF  1024
#define NLAY 6
#define BB   8
#define LL   1024
#define TT   (BB * LL)     /* 8192 tokens */
#define TOPK 256
#define EPSF 1e-5f

/* ------------------------------------------------------------------ */
/* scratch (static device globals: no runtime allocation)             */
/* ------------------------------------------------------------------ */
__device__ float g_H[TT * DM];
__device__ float g_S[TT * DM];
__device__ float g_QKV[TT * 3 * DM];
__device__ float g_O[TT * DM];
__device__ float g_P[TT * DM];
__device__ float g_F[TT * DFF];
__device__ float g_VOL[BB * DFF];

/* ------------------------------------------------------------------ */
/* embed: h = x @ in_w + in_b + PE                                     */
/* ------------------------------------------------------------------ */
__global__ void embed_kernel(const float* __restrict__ x,
                             const float* __restrict__ in_w,
                             const float* __restrict__ in_b) {
    int t = blockIdx.x;
    int d = threadIdx.x;
    int l = t & (LL - 1);
    const float c = -9.210340371976184f / 256.0f;  /* -ln(10000)/256 */
    float div = expf((float)(d & ~1) * c);
    float ang = (float)l * div;
    float pe = (d & 1) ? cosf(ang) : sinf(ang);
    g_H[(size_t)t * DM + d] =
        x[t * 2 + 0] * in_w[d] + x[t * 2 + 1] * in_w[DM + d] + in_b[d] + pe;
}

/* ------------------------------------------------------------------ */
/* LayerNorm: warp per token, 8 tokens per 256-thread block            */
/* ------------------------------------------------------------------ */
__device__ __forceinline__ void warp_reduce_2(float& s, float& q) {
#pragma unroll
    for (int o = 16; o > 0; o >>= 1) {
        s += __shfl_xor_sync(0xffffffffu, s, o);
        q += __shfl_xor_sync(0xffffffffu, q, o);
    }
}

__device__ __forceinline__ float4 ln_apply(float4 v, float mean, float r,
                                           float4 g, float4 b) {
    float4 o;
    o.x = (v.x - mean) * r * g.x + b.x;
    o.y = (v.y - mean) * r * g.y + b.y;
    o.z = (v.z - mean) * r * g.z + b.z;
    o.w = (v.w - mean) * r * g.w + b.w;
    return o;
}

/* dst = LN(src) */
__global__ void ln_kernel(const float* __restrict__ src,
                          const float* __restrict__ g,
                          const float* __restrict__ bt,
                          float* __restrict__ dst) {
    int w = threadIdx.x >> 5, lane = threadIdx.x & 31;
    size_t t = (size_t)blockIdx.x * 8 + w;
    const float4* s4 = (const float4*)(src + t * DM);
    float4 a = s4[lane * 2], b = s4[lane * 2 + 1];
    float s = a.x + a.y + a.z + a.w + b.x + b.y + b.z + b.w;
    float q = a.x*a.x + a.y*a.y + a.z*a.z + a.w*a.w
            + b.x*b.x + b.y*b.y + b.z*b.z + b.w*b.w;
    warp_reduce_2(s, q);
    float mean = s * (1.f / DM);
    float var  = q * (1.f / DM) - mean * mean;
    float r = rsqrtf(var + EPSF);
    float4 g0 = ((const float4*)g)[lane * 2], g1 = ((const float4*)g)[lane * 2 + 1];
    float4 b0 = ((const float4*)bt)[lane * 2], b1 = ((const float4*)bt)[lane * 2 + 1];
    float4* d4 = (float4*)(dst + t * DM);
    d4[lane * 2]     = ln_apply(a, mean, r, g0, b0);
    d4[lane * 2 + 1] = ln_apply(b, mean, r, g1, b1);
}

/* H += LN(P + S) */
__global__ void lna_kernel(const float* __restrict__ Pp,
                           const float* __restrict__ Sp,
                           const float* __restrict__ g,
                           const float* __restrict__ bt,
                           float* __restrict__ H) {
    int w = threadIdx.x >> 5, lane = threadIdx.x & 31;
    size_t t = (size_t)blockIdx.x * 8 + w;
    const float4* p4 = (const float4*)(Pp + t * DM);
    const float4* s4 = (const float4*)(Sp + t * DM);
    float4 pa = p4[lane * 2], pb = p4[lane * 2 + 1];
    float4 sa = s4[lane * 2], sb = s4[lane * 2 + 1];
    float4 a, b;
    a.x = pa.x + sa.x; a.y = pa.y + sa.y; a.z = pa.z + sa.z; a.w = pa.w + sa.w;
    b.x = pb.x + sb.x; b.y = pb.y + sb.y; b.z = pb.z + sb.z; b.w = pb.w + sb.w;
    float s = a.x + a.y + a.z + a.w + b.x + b.y + b.z + b.w;
    float q = a.x*a.x + a.y*a.y + a.z*a.z + a.w*a.w
            + b.x*b.x + b.y*b.y + b.z*b.z + b.w*b.w;
    warp_reduce_2(s, q);
    float mean = s * (1.f / DM);
    float var  = q * (1.f / DM) - mean * mean;
    float r = rsqrtf(var + EPSF);
    float4 g0 = ((const float4*)g)[lane * 2], g1 = ((const float4*)g)[lane * 2 + 1];
    float4 b0 = ((const float4*)bt)[lane * 2], b1 = ((const float4*)bt)[lane * 2 + 1];
    float4 r0 = ln_apply(a, mean, r, g0, b0);
    float4 r1 = ln_apply(b, mean, r, g1, b1);
    float4* h4 = (float4*)(H + t * DM);
    float4 h0 = h4[lane * 2], h1 = h4[lane * 2 + 1];
    h0.x += r0.x; h0.y += r0.y; h0.z += r0.z; h0.w += r0.w;
    h1.x += r1.x; h1.y += r1.y; h1.z += r1.z; h1.w += r1.w;
    h4[lane * 2]     = h0;
    h4[lane * 2 + 1] = h1;
}

/* ------------------------------------------------------------------ */
/* tiled SGEMM: C[M,N] (=|+=) A[M,K] @ B[K,N] + bias                   */
/* BM=128, BN=128, BK=16, 256 threads, 8x8 per-thread tile             */
/* ------------------------------------------------------------------ */
template <bool ADD, bool USEVOL>
__global__ void gemm_kernel(const float* __restrict__ A,
                            const float* __restrict__ Bw,
                            const float* __restrict__ bias,
                            float* __restrict__ C,
                            int M, int N, int K) {
    __shared__ float As[16][128];
    __shared__ float Bs[16][128];

    int tid = threadIdx.x;
    int tx = tid & 15;
    int ty = tid >> 4;
    int bn0 = blockIdx.x * 128;
    int bm0 = blockIdx.y * 128;

    const float* volp = USEVOL ? (g_VOL + (size_t)((bm0 >> 10) << 10)) : (const float*)0;

    float acc[8][8];
#pragma unroll
    for (int i = 0; i < 8; i++)
#pragma unroll
        for (int j = 0; j < 8; j++) acc[i][j] = 0.f;

    int ar = tid >> 1;
    int ac = (tid & 1) * 8;
    int br = tid >> 4;
    int bc = (tid & 15) * 8;

    for (int k0 = 0; k0 < K; k0 += 16) {
        float4 a0 = *(const float4*)&A[(size_t)(bm0 + ar) * K + k0 + ac];
        float4 a1 = *(const float4*)&A[(size_t)(bm0 + ar) * K + k0 + ac + 4];
        if (USEVOL) {
            a0.x *= volp[k0 + ac + 0]; a0.y *= volp[k0 + ac + 1];
            a0.z *= volp[k0 + ac + 2]; a0.w *= volp[k0 + ac + 3];
            a1.x *= volp[k0 + ac + 4]; a1.y *= volp[k0 + ac + 5];
            a1.z *= volp[k0 + ac + 6]; a1.w *= volp[k0 + ac + 7];
        }
        As[ac + 0][ar] = a0.x; As[ac + 1][ar] = a0.y;
        As[ac + 2][ar] = a0.z; As[ac + 3][ar] = a0.w;
        As[ac + 4][ar] = a1.x; As[ac + 5][ar] = a1.y;
        As[ac + 6][ar] = a1.z; As[ac + 7][ar] = a1.w;

        float4 b0 = *(const float4*)&Bw[(size_t)(k0 + br) * N + bn0 + bc];
        float4 b1 = *(const float4*)&Bw[(size_t)(k0 + br) * N + bn0 + bc + 4];
        *(float4*)&Bs[br][bc]     = b0;
        *(float4*)&Bs[br][bc + 4] = b1;

        __syncthreads();
#pragma unroll
        for (int kk = 0; kk < 16; kk++) {
            float a[8], bb[8];
            *(float4*)&a[0]  = *(const float4*)&As[kk][ty * 8];
            *(float4*)&a[4]  = *(const float4*)&As[kk][ty * 8 + 4];
            *(float4*)&bb[0] = *(const float4*)&Bs[kk][tx * 8];
            *(float4*)&bb[4] = *(const float4*)&Bs[kk][tx * 8 + 4];
#pragma unroll
            for (int i = 0; i < 8; i++)
#pragma unroll
                for (int j = 0; j < 8; j++)
                    acc[i][j] += a[i] * bb[j];
        }
        __syncthreads();
    }

    float bia[8];
    *(float4*)&bia[0] = *(const float4*)&bias[bn0 + tx * 8];
    *(float4*)&bia[4] = *(const float4*)&bias[bn0 + tx * 8 + 4];

#pragma unroll
    for (int i = 0; i < 8; i++) {
        size_t row = (size_t)(bm0 + ty * 8 + i);
        float* cp = &C[row * N + bn0 + tx * 8];
        if (ADD) {
            float4 c0 = *(float4*)&cp[0];
            float4 c1 = *(float4*)&cp[4];
            c0.x += acc[i][0] + bia[0]; c0.y += acc[i][1] + bia[1];
            c0.z += acc[i][2] + bia[2]; c0.w += acc[i][3] + bia[3];
            c1.x += acc[i][4] + bia[4]; c1.y += acc[i][5] + bia[5];
            c1.z += acc[i][6] + bia[6]; c1.w += acc[i][7] + bia[7];
            *(float4*)&cp[0] = c0; *(float4*)&cp[4] = c1;
        } else {
            float4 c0, c1;
            c0.x = acc[i][0] + bia[0]; c0.y = acc[i][1] + bia[1];
            c0.z = acc[i][2] + bia[2]; c0.w = acc[i][3] + bia[3];
            c1.x = acc[i][4] + bia[4]; c1.y = acc[i][5] + bia[5];
            c1.z = acc[i][6] + bia[6]; c1.w = acc[i][7] + bia[7];
            *(float4*)&cp[0] = c0; *(float4*)&cp[4] = c1;
        }
    }
}

/* ------------------------------------------------------------------ */
/* ProbSparse attention, 16 queries per 512-thread block               */
/* smem floats: sc 16384 | kbuf 4608 | Qs 576 | hist/list 4096 | tb 160*/
/* ------------------------------------------------------------------ */
#define SC_OFF    0
#define KBUF_OFF  16384
#define QS_OFF    20992
#define HIST_OFF  21568
#define TB_OFF    25664
#define ATTN_SMEM (25824 * 4)

__device__ __forceinline__ unsigned f2u(float f) {
    unsigned u = __float_as_uint(f);
    return (u & 0x80000000u) ? ~u : (u | 0x80000000u);
}
__device__ __forceinline__ float u2f(unsigned x) {
    unsigned v = (x & 0x80000000u) ? (x ^ 0x80000000u) : ~x;
    return __uint_as_float(v);
}

__global__ void __launch_bounds__(512, 2)
attn_kernel(const float* __restrict__ QKV, float* __restrict__ O) {
    extern __shared__ float smx[];
    float* sc   = smx + SC_OFF;
    float* kbuf = smx + KBUF_OFF;
    float* Qs   = smx + QS_OFF;
    int*   histb = (int*)(smx + HIST_OFF);
    int*   tb    = (int*)(smx + TB_OFF);

    int tid = threadIdx.x, lane = tid & 31, w = tid >> 5;
    int bh = blockIdx.y, b = bh >> 3, h = bh & 7;
    int qbase = blockIdx.x * 16;
    size_t tokbase = (size_t)b * LL;
    const float* base = QKV + tokbase * 768 + h * 32;

    /* stage Q tile: 16 x 32, pitch 36 */
    {
        int q = tid >> 5, d = tid & 31;
        Qs[q * 36 + d] = base[(size_t)(qbase + q) * 768 + d];
    }

    const float scale = 0.17677669529663687f; /* 1/sqrt(32) */
    float* row = sc + w * 1024;
    int group = w >> 2;           /* key subgroup 0..3 within tile */
    int q0 = (w & 3) * 4;         /* this warp scores 4 queries    */

    /* ---------------- phase 1: scores (K rows in registers) -------- */
    for (int kt = 0; kt < 8; kt++) {
        __syncthreads();
        {
            int key = tid >> 2, dp = (tid & 3) * 8;
            const float* src = base + (size_t)(kt * 128 + key) * 768 + 256 + dp;
            float4 v0 = *(const float4*)src;
            float4 v1 = *(const float4*)(src + 4);
            *(float4*)&kbuf[key * 36 + dp]     = v0;
            *(float4*)&kbuf[key * 36 + dp + 4] = v1;
        }
        __syncthreads();
        float4 kr[8];
        const float4* kp = (const float4*)&kbuf[(group * 32 + lane) * 36];
#pragma unroll
        for (int i = 0; i < 8; i++) kr[i] = kp[i];
#pragma unroll
        for (int j = 0; j < 4; j++) {
            const float4* qp = (const float4*)&Qs[(q0 + j) * 36];
            float s = 0.f;
#pragma unroll
            for (int i = 0; i < 8; i++) {
                float4 qv = qp[i];
                s += qv.x * kr[i].x + qv.y * kr[i].y
                   + qv.z * kr[i].z + qv.w * kr[i].w;
            }
            sc[(q0 + j) * 1024 + kt * 128 + group * 32 + lane] = s * scale;
        }
    }
    __syncthreads();

    /* -------- phase 2: exact 256-th largest (4-pass radix) --------- */
    int* hw = histb + w * 256;
    const float4* row4 = (const float4*)row;
    unsigned prefix = 0, umax = 0;
    int krem = TOPK;
#pragma unroll
    for (int pass = 0; pass < 4; pass++) {
        int shift = 24 - 8 * pass;
        for (int i = lane; i < 256; i += 32) hw[i] = 0;
        __syncwarp();
        for (int j4 = lane; j4 < 256; j4 += 32) {
            float4 s4 = row4[j4];
            unsigned u0 = f2u(s4.x), u1 = f2u(s4.y);
            unsigned u2 = f2u(s4.z), u3 = f2u(s4.w);
            if (pass == 0) {
                umax = max(max(umax, u0), max(u1, max(u2, u3)));
                atomicAdd(&hw[u0 >> 24], 1);
                atomicAdd(&hw[u1 >> 24], 1);
                atomicAdd(&hw[u2 >> 24], 1);
                atomicAdd(&hw[u3 >> 24], 1);
            } else {
                unsigned hi = (prefix >> shift) >> 8;
                if (((u0 >> shift) >> 8) == hi) atomicAdd(&hw[(u0 >> shift) & 255], 1);
                if (((u1 >> shift) >> 8) == hi) atomicAdd(&hw[(u1 >> shift) & 255], 1);
                if (((u2 >> shift) >> 8) == hi) atomicAdd(&hw[(u2 >> shift) & 255], 1);
                if (((u3 >> shift) >> 8) == hi) atomicAdd(&hw[(u3 >> shift) & 255], 1);
            }
        }
        __syncwarp();
        /* warp-parallel bin selection (descending suffix counts) */
        int gs = 0;
#pragma unroll
        for (int i = 0; i < 8; i++) gs += hw[255 - (lane * 8 + i)];
        int S = gs;
#pragma unroll
        for (int off = 1; off < 32; off <<= 1) {
            int t2 = __shfl_up_sync(0xffffffffu, S, off);
            if (lane >= off) S += t2;
        }
        unsigned bal = __ballot_sync(0xffffffffu, S >= krem);
        int L = __ffs(bal) - 1;
        int SL  = __shfl_sync(0xffffffffu, S, L);
        int gsL = __shfl_sync(0xffffffffu, gs, L);
        int c = SL - gsL, selbin = 255 - L * 8, knew = krem;
#pragma unroll
        for (int i = 0; i < 8; i++) {
            int bn = 255 - (L * 8 + i);
            int hv = hw[bn];
            c += hv;
            if (c >= krem) { selbin = bn; knew = krem - (c - hv); break; }
        }
        prefix |= ((unsigned)selbin) << shift;
        krem = knew;
    }
#pragma unroll
    for (int o = 16; o > 0; o >>= 1)
        umax = max(umax, __shfl_xor_sync(0xffffffffu, umax, o));
    float lmax = u2f(umax);
    unsigned thr = prefix;

    /* -------- softmax + packed (weight|key) compaction -------------- */
    /* entry = fp32 weight with low 10 mantissa bits replaced by key    */
    float* lstf = (float*)hw;            /* hist region is dead now     */
    float zs = 0.f;
    int cnt = 0;
    if (lane == 0) tb[w * 10] = 0;
    unsigned ltm = (1u << lane) - 1u;
    for (int kt = 0; kt < 8; kt++) {
        float4 s4 = row4[kt * 32 + lane];
        bool b0 = f2u(s4.x) >= thr, b1 = f2u(s4.y) >= thr;
        bool b2 = f2u(s4.z) >= thr, b3 = f2u(s4.w) >= thr;
        float w0 = b0 ? expf(s4.x - lmax) : 0.f;
        float w1 = b1 ? expf(s4.y - lmax) : 0.f;
        float w2 = b2 ? expf(s4.z - lmax) : 0.f;
        float w3 = b3 ? expf(s4.w - lmax) : 0.f;
        zs += w0 + w1 + w2 + w3;
        int key0 = kt * 128 + lane * 4;
        unsigned m0 = __ballot_sync(0xffffffffu, b0);
        unsigned m1 = __ballot_sync(0xffffffffu, b1);
        unsigned m2 = __ballot_sync(0xffffffffu, b2);
        unsigned m3 = __ballot_sync(0xffffffffu, b3);
        int c0 = __popc(m0), c1 = __popc(m1), c2 = __popc(m2), c3 = __popc(m3);
        int p0 = cnt + __popc(m0 & ltm);
        int p1 = cnt + c0 + __popc(m1 & ltm);
        int p2 = cnt + c0 + c1 + __popc(m2 & ltm);
        int p3 = cnt + c0 + c1 + c2 + __popc(m3 & ltm);
        if (b0 && p0 < 256)
            lstf[p0] = __uint_as_float((__float_as_uint(w0) & ~1023u) | (unsigned)(key0));
        if (b1 && p1 < 256)
            lstf[p1] = __uint_as_float((__float_as_uint(w1) & ~1023u) | (unsigned)(key0 + 1));
        if (b2 && p2 < 256)
            lstf[p2] = __uint_as_float((__float_as_uint(w2) & ~1023u) | (unsigned)(key0 + 2));
        if (b3 && p3 < 256)
            lstf[p3] = __uint_as_float((__float_as_uint(w3) & ~1023u) | (unsigned)(key0 + 3));
        cnt += c0 + c1 + c2 + c3;
        if (lane == 0) tb[w * 10 + kt + 1] = min(cnt, 256);
    }
#pragma unroll
    for (int o = 16; o > 0; o >>= 1) zs += __shfl_xor_sync(0xffffffffu, zs, o);
    float rz = 1.f / zs;
    __syncwarp();

    /* -------- phase 3: O = attn @ V over packed list ---------------- */
    float oacc = 0.f;
    for (int kt = 0; kt < 8; kt++) {
        __syncthreads();
        {
            int key = tid >> 2, dp = (tid & 3) * 8;
            const float* src = base + (size_t)(kt * 128 + key) * 768 + 512 + dp;
            float4 v0 = *(const float4*)src;
            float4 v1 = *(const float4*)(src + 4);
            *(float4*)&kbuf[key * 36 + dp]     = v0;
            *(float4*)&kbuf[key * 36 + dp + 4] = v1;
        }
        __syncthreads();
        int i0 = tb[w * 10 + kt], i1 = tb[w * 10 + kt + 1];
        for (int i = i0; i < i1; i++) {
            unsigned eb = __float_as_uint(lstf[i]);   /* broadcast, 1 wf */
            float wt = __uint_as_float(eb);
            int key = eb & 1023;
            oacc = fmaf(wt, kbuf[(key & 127) * 36 + lane], oacc);
        }
    }
    O[(tokbase + qbase + w) * 256 + h * 32 + lane] = oacc * rz;
}

/* ------------------------------------------------------------------ */
/* Volatilite: vol[b,j] = std over L of F[b,:,j]                       */
/* ------------------------------------------------------------------ */
__global__ void vol_kernel(const float* __restrict__ F) {
    int tx = threadIdx.x & 127;
    int ty = threadIdx.x >> 7;
    int j = blockIdx.x * 128 + tx;
    int b = blockIdx.y;
    float s = 0.f, ss = 0.f;
    for (int l = ty; l < LL; l += 4) {
        float v = F[((size_t)(b * LL + l)) * DFF + j];
        s += v; ss += v * v;
    }
    __shared__ float sh1[4][128], sh2[4][128];
    sh1[ty][tx] = s; sh2[ty][tx] = ss;
    __syncthreads();
    if (ty == 0) {
        s  = sh1[0][tx] + sh1[1][tx] + sh1[2][tx] + sh1[3][tx];
        ss = sh2[0][tx] + sh2[1][tx] + sh2[2][tx] + sh2[3][tx];
        float mean = s * (1.f / LL);
        float var  = ss * (1.f / LL) - mean * mean;
        g_VOL[b * DFF + j] = sqrtf(fmaxf(var, 0.f));
    }
}

/* ------------------------------------------------------------------ */
extern "C" void kernel_launch(void* const* d_in, const int* in_sizes, int n_in,
                              void* d_out, int out_size) {
    const float* x     = (const float*)d_in[0];
    const float* in_w  = (const float*)d_in[1];
    const float* in_b  = (const float*)d_in[2];
    const float* ln1_g = (const float*)d_in[3];
    const float* ln1_b = (const float*)d_in[4];
    const float* qkv_w = (const float*)d_in[5];
    const float* qkv_b = (const float*)d_in[6];
    const float* out_w = (const float*)d_in[7];
    const float* out_b = (const float*)d_in[8];
    const float* lna_g = (const float*)d_in[9];
    const float* lna_b = (const float*)d_in[10];
    const float* ln2_g = (const float*)d_in[11];
    const float* ln2_b = (const float*)d_in[12];
    const float* ff1_w = (const float*)d_in[13];
    const float* ff1_b = (const float*)d_in[14];
    const float* ff2_w = (const float*)d_in[15];
    const float* ff2_b = (const float*)d_in[16];
    const float* lnf_g = (const float*)d_in[17];
    const float* lnf_b = (const float*)d_in[18];
    float* out = (float*)d_out;

    float *H, *S, *Q, *O, *P, *F;
    cudaGetSymbolAddress((void**)&H, g_H);
    cudaGetSymbolAddress((void**)&S, g_S);
    cudaGetSymbolAddress((void**)&Q, g_QKV);
    cudaGetSymbolAddress((void**)&O, g_O);
    cudaGetSymbolAddress((void**)&P, g_P);
    cudaGetSymbolAddress((void**)&F, g_F);

    cudaFuncSetAttribute((const void*)attn_kernel,
                         cudaFuncAttributeMaxDynamicSharedMemorySize, ATTN_SMEM);

    embed_kernel<<<TT, 256>>>(x, in_w, in_b);

    for (int layer = 0; layer < NLAY; layer++) {
        /* s2 = LN1(h) */
        ln_kernel<<<TT / 8, 256>>>(H, ln1_g, ln1_b, S);
        /* qkv = s2 @ qkv_w + qkv_b */
        gemm_kernel<false, false><<<dim3(768 / 128, TT / 128), 256>>>(
            S, qkv_w, qkv_b, Q, TT, 768, DM);
        /* probsparse attention */
        attn_kernel<<<dim3(LL / 16, BB * NH), 512, ATTN_SMEM>>>(Q, O);
        /* P = O @ out_w + out_b */
        gemm_kernel<false, false><<<dim3(256 / 128, TT / 128), 256>>>(
            O, out_w, out_b, P, TT, DM, DM);
        /* h += LN(P + s2) */
        lna_kernel<<<TT / 8, 256>>>(P, S, lna_g, lna_b, H);
        /* s2 = LN2(h) */
        ln_kernel<<<TT / 8, 256>>>(H, ln2_g, ln2_b, S);
        /* F = s2 @ ff1_w + ff1_b */
        gemm_kernel<false, false><<<dim3(1024 / 128, TT / 128), 256>>>(
            S, ff1_w, ff1_b, F, TT, DFF, DM);
        /* vol[b,j] */
        vol_kernel<<<dim3(DFF / 128, BB), 512>>>(F);
        /* h += (F * vol) @ ff2_w + ff2_b */
        gemm_kernel<true, true><<<dim3(256 / 128, TT / 128), 256>>>(
            F, ff2_w, ff2_b, H, TT, DM, DFF);
    }

    /* out = LN_f(h) */
    ln_kernel<<<TT / 8, 256>>>(H, lnf_g, lnf_b, out);
}